// round 2
// baseline (speedup 1.0000x reference)
#include <cuda_runtime.h>
#include <stdint.h>

// JAX threefry convention: 1 = jax_threefry_partitionable=True,
// 0 = original (halved-counter) convention.
// R1: partitionable gave rel_err 1.06e-3 ~ sqrt(2)*sigma/sqrt(B) => selections
// were wrong => reference env uses the ORIGINAL convention. Flip to 0.
#define JAX_PARTITIONABLE 0

#define MAXB 8192
#define MAXD 512
#define NNEG 8

// Scratch (no cudaMalloc allowed)
__device__ float         g_f[MAXB * MAXD];     // normalized features (16 MB)
__device__ unsigned char g_lab[MAXB];
__device__ int           g_posj[MAXB];
__device__ int           g_negidx[MAXB * NNEG];
__device__ float         g_loss[MAXB];

// ---------------- Threefry-2x32 (20 rounds) ----------------
__host__ __device__ __forceinline__ void threefry2x32(
    uint32_t k0, uint32_t k1, uint32_t x0, uint32_t x1,
    uint32_t* o0, uint32_t* o1)
{
    uint32_t ks2 = k0 ^ k1 ^ 0x1BD11BDAu;
    x0 += k0; x1 += k1;
#define TF_ROTL(v, r) (((v) << (r)) | ((v) >> (32 - (r))))
#define TF_RND(r) { x0 += x1; x1 = TF_ROTL(x1, r); x1 ^= x0; }
    TF_RND(13) TF_RND(15) TF_RND(26) TF_RND(6)  x0 += k1;  x1 += ks2 + 1u;
    TF_RND(17) TF_RND(29) TF_RND(16) TF_RND(24) x0 += ks2; x1 += k0  + 2u;
    TF_RND(13) TF_RND(15) TF_RND(26) TF_RND(6)  x0 += k0;  x1 += k1  + 3u;
    TF_RND(17) TF_RND(29) TF_RND(16) TF_RND(24) x0 += k1;  x1 += ks2 + 4u;
    TF_RND(13) TF_RND(15) TF_RND(26) TF_RND(6)  x0 += ks2; x1 += k0  + 5u;
#undef TF_RND
#undef TF_ROTL
    *o0 = x0; *o1 = x1;
}

__device__ __forceinline__ uint32_t random_bits32(
    uint32_t k0, uint32_t k1, uint64_t n, uint64_t half)
{
#if JAX_PARTITIONABLE
    uint32_t o0, o1;
    threefry2x32(k0, k1, (uint32_t)(n >> 32), (uint32_t)n, &o0, &o1);
    return o0 ^ o1;
#else
    uint32_t o0, o1;
    if (n < half) {
        threefry2x32(k0, k1, (uint32_t)n, (uint32_t)(n + half), &o0, &o1);
        return o0;
    } else {
        threefry2x32(k0, k1, (uint32_t)(n - half), (uint32_t)n, &o0, &o1);
        return o1;
    }
#endif
}

// ---------------- Kernel 1: row L2-normalize + label cast ----------------
__global__ void k_normalize(const float* __restrict__ feat,
                            const long long* __restrict__ labels,
                            int B, int D)
{
    int i = blockIdx.x;
    int tid = threadIdx.x;               // 128 threads
    const float4* src = (const float4*)(feat + (size_t)i * D);
    float4*       dst = (float4*)(g_f + (size_t)i * D);
    int n4 = D >> 2;

    float ss = 0.0f;
    for (int c = tid; c < n4; c += blockDim.x) {
        float4 v = src[c];
        ss += v.x * v.x + v.y * v.y + v.z * v.z + v.w * v.w;
    }
    #pragma unroll
    for (int o = 16; o; o >>= 1) ss += __shfl_xor_sync(0xffffffffu, ss, o);

    __shared__ float sw[4];
    if ((tid & 31) == 0) sw[tid >> 5] = ss;
    __syncthreads();
    float tot = sw[0] + sw[1] + sw[2] + sw[3];
    float inv = 1.0f / fmaxf(sqrtf(tot), 1e-12f);

    for (int c = tid; c < n4; c += blockDim.x) {
        float4 v = src[c];
        float4 o4;
        o4.x = v.x * inv; o4.y = v.y * inv; o4.z = v.z * inv; o4.w = v.w * inv;
        dst[c] = o4;
    }
    if (tid == 0) g_lab[i] = (unsigned char)labels[i];
}

// ---------------- Kernel 2: gumbel argmax (pos) + gumbel top-8 (neg) ----------------
// Ordering of gumbel == ordering of (bits>>9) with lower-index tie-break.
// Pack: key = ((bits>>9) << 13) | (B-1-j)   (23 + 13 bits, fits u64)
__global__ void k_select(int B,
                         uint32_t kp0, uint32_t kp1,
                         uint32_t kn0, uint32_t kn1)
{
    int i = blockIdx.x;
    int tid = threadIdx.x;               // 256 threads
    __shared__ unsigned char slab[MAXB];
    __shared__ unsigned long long sred[256];

    for (int j = tid; j < B; j += 256) slab[j] = g_lab[j];
    __syncthreads();

    unsigned char mylab = slab[i];
    uint64_t half = ((uint64_t)B * (uint64_t)B) >> 1;
    uint64_t rowbase = (uint64_t)i * (uint64_t)B;

    unsigned long long bestpos = 0ull;
    unsigned long long top[NNEG];
    #pragma unroll
    for (int r = 0; r < NNEG; r++) top[r] = 0ull;

    for (int j = tid; j < B; j += 256) {
        if (j == i) continue;
        bool same = (slab[j] == mylab);
        uint32_t k0 = same ? kp0 : kn0;
        uint32_t k1 = same ? kp1 : kn1;
        uint32_t bits = random_bits32(k0, k1, rowbase + (uint64_t)j, half);
        unsigned long long packed =
            ((unsigned long long)(bits >> 9) << 13) |
            (unsigned long long)(B - 1 - j);
        if (same) {
            if (packed > bestpos) bestpos = packed;
        } else {
            if (packed > top[NNEG - 1]) {
                top[NNEG - 1] = packed;
                #pragma unroll
                for (int r = NNEG - 1; r > 0; r--) {
                    if (top[r] > top[r - 1]) {
                        unsigned long long t = top[r];
                        top[r] = top[r - 1]; top[r - 1] = t;
                    }
                }
            }
        }
    }

    // ---- positive argmax reduce ----
    sred[tid] = bestpos;
    __syncthreads();
    for (int off = 128; off; off >>= 1) {
        if (tid < off && sred[tid + off] > sred[tid]) sred[tid] = sred[tid + off];
        __syncthreads();
    }
    if (tid == 0) {
        unsigned long long bp = sred[0];
        g_posj[i] = (bp == 0ull) ? 0 : (B - 1 - (int)(bp & 0x1FFFull));
    }
    __syncthreads();

    // ---- negative top-8 reduce (merge heads of per-thread sorted lists) ----
    for (int r = 0; r < NNEG; r++) {
        sred[tid] = top[0];
        __syncthreads();
        for (int off = 128; off; off >>= 1) {
            if (tid < off && sred[tid + off] > sred[tid]) sred[tid] = sred[tid + off];
            __syncthreads();
        }
        unsigned long long w = sred[0];
        if (top[0] == w && w != 0ull) {  // unique owner (j embedded in packed)
            #pragma unroll
            for (int q = 0; q < NNEG - 1; q++) top[q] = top[q + 1];
            top[NNEG - 1] = 0ull;
        }
        if (tid == 0) g_negidx[i * NNEG + r] = B - 1 - (int)(w & 0x1FFFull);
        __syncthreads();
    }
}

// ---------------- Kernel 3: 9 dots + top-3 + logsumexp per row ----------------
__global__ void k_loss(int B, int D)
{
    int i = blockIdx.x;
    int tid  = threadIdx.x;              // 128 threads
    int lane = tid & 31;
    int w    = tid >> 5;
    __shared__ float sf[MAXD];
    __shared__ float sdots[12];
    int n4 = D >> 2;

    for (int c = tid; c < n4; c += 128)
        ((float4*)sf)[c] = ((const float4*)(g_f + (size_t)i * D))[c];
    __syncthreads();

    for (int t = w; t < 1 + NNEG; t += 4) {
        int j = (t == 0) ? g_posj[i] : g_negidx[i * NNEG + (t - 1)];
        const float4* fr = (const float4*)(g_f + (size_t)j * D);
        float acc = 0.0f;
        for (int c = lane; c < n4; c += 32) {
            float4 a = ((float4*)sf)[c];
            float4 b = fr[c];
            acc += a.x * b.x + a.y * b.y + a.z * b.z + a.w * b.w;
        }
        #pragma unroll
        for (int o = 16; o; o >>= 1) acc += __shfl_xor_sync(0xffffffffu, acc, o);
        if (lane == 0) sdots[t] = acc;
    }
    __syncthreads();

    if (tid == 0) {
        float pos = sdots[0] * 2.0f;     // / TEMPERATURE (0.5)
        float s[NNEG];
        #pragma unroll
        for (int q = 0; q < NNEG; q++) s[q] = sdots[1 + q];
        float hard[3];
        #pragma unroll
        for (int r = 0; r < 3; r++) {    // stable top-3 (lower index wins ties)
            int bi = 0; float bv = s[0];
            #pragma unroll
            for (int q = 1; q < NNEG; q++) if (s[q] > bv) { bv = s[q]; bi = q; }
            hard[r] = bv * 2.0f;
            s[bi] = -3.0e38f;
        }
        float mx = fmaxf(fmaxf(pos, hard[0]), fmaxf(hard[1], hard[2]));
        float sum = expf(pos - mx) + expf(hard[0] - mx) +
                    expf(hard[1] - mx) + expf(hard[2] - mx);
        g_loss[i] = mx + logf(sum) - pos;
    }
}

// ---------------- Kernel 4: mean reduce ----------------
__global__ void k_reduce(float* __restrict__ out, int B)
{
    __shared__ float s[256];
    int tid = threadIdx.x;
    float a = 0.0f;
    for (int i = tid; i < B; i += 256) a += g_loss[i];
    s[tid] = a;
    __syncthreads();
    for (int off = 128; off; off >>= 1) {
        if (tid < off) s[tid] += s[tid + off];
        __syncthreads();
    }
    if (tid == 0) out[0] = s[0] / (float)B;
}

// ---------------- Launch ----------------
extern "C" void kernel_launch(void* const* d_in, const int* in_sizes, int n_in,
                              void* d_out, int out_size)
{
    const float*     feat   = (const float*)d_in[0];
    const long long* labels = (const long long*)d_in[1];
    int B = in_sizes[1];
    int D = in_sizes[0] / B;

    // seed 42 -> raw key (0, 42); derive kp (positives), kn (negatives)
    uint32_t kp0, kp1, kn0, kn1;
#if JAX_PARTITIONABLE
    // fold-like split: key_i = threefry(key, (0, i))
    threefry2x32(0u, 42u, 0u, 0u, &kp0, &kp1);
    threefry2x32(0u, 42u, 0u, 1u, &kn0, &kn1);
#else
    // original split: counts=[0,1,2,3] -> pairs (0,2),(1,3); kp=(a0,a1), kn=(b0,b1)
    uint32_t a0, b0, a1, b1;
    threefry2x32(0u, 42u, 0u, 2u, &a0, &b0);
    threefry2x32(0u, 42u, 1u, 3u, &a1, &b1);
    kp0 = a0; kp1 = a1; kn0 = b0; kn1 = b1;
#endif

    k_normalize<<<B, 128>>>(feat, labels, B, D);
    k_select  <<<B, 256>>>(B, kp0, kp1, kn0, kn1);
    k_loss    <<<B, 128>>>(B, D);
    k_reduce  <<<1, 256>>>((float*)d_out, B);
}

// round 3
// speedup vs baseline: 1.1989x; 1.1989x over previous
#include <cuda_runtime.h>
#include <stdint.h>

// Fixed problem shape: features [8192, 512], labels [8192] in [0,64)
#define NB 8192
#define ND 512
#define NNEG 8
#define HALFC 33554432u   // (8192*8192)/2, fits u32

// Scratch (no cudaMalloc allowed)
__device__ float         g_f[NB * ND];       // normalized features (16 MB)
__device__ unsigned char g_lab[NB];
__device__ int           g_posj[NB];
__device__ int           g_negidx[NB * NNEG];
__device__ float         g_loss[NB];
__device__ int           g_done;             // zero-init; last k_loss block resets

// ---------------- Threefry-2x32 (20 rounds), original JAX convention ----------
__host__ __device__ __forceinline__ void threefry2x32(
    uint32_t k0, uint32_t k1, uint32_t x0, uint32_t x1,
    uint32_t* o0, uint32_t* o1)
{
    uint32_t ks2 = k0 ^ k1 ^ 0x1BD11BDAu;
    x0 += k0; x1 += k1;
#define TF_ROTL(v, r) (((v) << (r)) | ((v) >> (32 - (r))))
#define TF_RND(r) { x0 += x1; x1 = TF_ROTL(x1, r); x1 ^= x0; }
    TF_RND(13) TF_RND(15) TF_RND(26) TF_RND(6)  x0 += k1;  x1 += ks2 + 1u;
    TF_RND(17) TF_RND(29) TF_RND(16) TF_RND(24) x0 += ks2; x1 += k0  + 2u;
    TF_RND(13) TF_RND(15) TF_RND(26) TF_RND(6)  x0 += k0;  x1 += k1  + 3u;
    TF_RND(17) TF_RND(29) TF_RND(16) TF_RND(24) x0 += k1;  x1 += ks2 + 4u;
    TF_RND(13) TF_RND(15) TF_RND(26) TF_RND(6)  x0 += ks2; x1 += k0  + 5u;
#undef TF_RND
#undef TF_ROTL
    *o0 = x0; *o1 = x1;
}

// pack: ordering of gumbel == ordering of (bits>>9); tie -> lower j wins.
__device__ __forceinline__ unsigned long long pack_key(uint32_t bits, int j)
{
    return ((unsigned long long)(bits >> 9) << 13) |
           (unsigned long long)(NB - 1 - j);
}

__device__ __forceinline__ unsigned long long warp_max_u64(unsigned long long v)
{
    #pragma unroll
    for (int o = 16; o; o >>= 1) {
        unsigned long long u = __shfl_xor_sync(0xffffffffu, v, o);
        if (u > v) v = u;
    }
    return v;
}

// ---------------- Kernel 1: row L2-normalize + label cast ----------------
__global__ void k_normalize(const float* __restrict__ feat,
                            const long long* __restrict__ labels)
{
    int i = blockIdx.x;
    int tid = threadIdx.x;               // 128 threads
    const float4* src = (const float4*)(feat + (size_t)i * ND);
    float4*       dst = (float4*)(g_f + (size_t)i * ND);
    const int n4 = ND >> 2;

    float ss = 0.0f;
    for (int c = tid; c < n4; c += 128) {
        float4 v = src[c];
        ss += v.x * v.x + v.y * v.y + v.z * v.z + v.w * v.w;
    }
    #pragma unroll
    for (int o = 16; o; o >>= 1) ss += __shfl_xor_sync(0xffffffffu, ss, o);

    __shared__ float sw[4];
    if ((tid & 31) == 0) sw[tid >> 5] = ss;
    __syncthreads();
    float tot = sw[0] + sw[1] + sw[2] + sw[3];
    float inv = 1.0f / fmaxf(sqrtf(tot), 1e-12f);

    for (int c = tid; c < n4; c += 128) {
        float4 v = src[c];
        float4 o4;
        o4.x = v.x * inv; o4.y = v.y * inv; o4.z = v.z * inv; o4.w = v.w * inv;
        dst[c] = o4;
    }
    if (tid == 0) g_lab[i] = (unsigned char)labels[i];
}

// ---------------- Kernel 2: row-PAIR gumbel selection ----------------
// Block b handles rows i_lo=b and i_hi=b+NB/2. In the original threefry
// convention, flat indices n and n+half share one threefry block:
// n -> o0, n+half -> o1. With half = NB^2/2, rows i and i+NB/2 at equal j
// share blocks, so ONE kn threefry serves both rows' negative gumbels.
// Positives (~1/64 of columns) are handled sparsely via a shared class list.
#define CLS_MAX 1024
__global__ __launch_bounds__(256) void k_select(
    uint32_t kp0, uint32_t kp1, uint32_t kn0, uint32_t kn1)
{
    const int i_lo = blockIdx.x;           // 0..4095
    const int i_hi = i_lo + (NB >> 1);
    const int tid = threadIdx.x, lane = tid & 31, wid = tid >> 5;

    __shared__ unsigned char slab[NB];
    __shared__ short slist[2][CLS_MAX];
    __shared__ int   scnt[2];
    __shared__ unsigned long long swin[2][64];
    __shared__ unsigned long long spos[2][8];

    for (int c = tid; c < NB / 4; c += 256)
        ((uint32_t*)slab)[c] = ((const uint32_t*)g_lab)[c];
    if (tid < 2) scnt[tid] = 0;
    __syncthreads();

    const unsigned char lab_lo = slab[i_lo];
    const unsigned char lab_hi = slab[i_hi];
    const uint32_t nbase = (uint32_t)i_lo * (uint32_t)NB;

    unsigned long long toplo[NNEG], tophi[NNEG];
    #pragma unroll
    for (int r = 0; r < NNEG; r++) { toplo[r] = 0ull; tophi[r] = 0ull; }

    for (int j = tid; j < NB; j += 256) {
        unsigned char lj = slab[j];
        if (lj == lab_lo) { int p = atomicAdd(&scnt[0], 1); if (p < CLS_MAX) slist[0][p] = (short)j; }
        if (lj == lab_hi) { int p = atomicAdd(&scnt[1], 1); if (p < CLS_MAX) slist[1][p] = (short)j; }

        uint32_t n = nbase + (uint32_t)j;
        uint32_t o0, o1;
        threefry2x32(kn0, kn1, n, n + HALFC, &o0, &o1);

        if (lj != lab_lo) {                          // negative for row lo
            unsigned long long p = pack_key(o0, j);
            if (p > toplo[NNEG - 1]) {
                toplo[NNEG - 1] = p;
                #pragma unroll
                for (int r = NNEG - 1; r > 0; r--)
                    if (toplo[r] > toplo[r - 1]) {
                        unsigned long long t = toplo[r]; toplo[r] = toplo[r - 1]; toplo[r - 1] = t;
                    }
            }
        }
        if (lj != lab_hi) {                          // negative for row hi
            unsigned long long p = pack_key(o1, j);
            if (p > tophi[NNEG - 1]) {
                tophi[NNEG - 1] = p;
                #pragma unroll
                for (int r = NNEG - 1; r > 0; r--)
                    if (tophi[r] > tophi[r - 1]) {
                        unsigned long long t = tophi[r]; tophi[r] = tophi[r - 1]; tophi[r - 1] = t;
                    }
            }
        }
    }
    __syncthreads();

    // ---- sparse positive loops (kp key) ----
    unsigned long long bp_lo = 0ull, bp_hi = 0ull;
    {
        int c0 = min(scnt[0], CLS_MAX);
        for (int t = tid; t < c0; t += 256) {
            int j = slist[0][t];
            if (j != i_lo) {
                uint32_t n = nbase + (uint32_t)j, o0, o1;
                threefry2x32(kp0, kp1, n, n + HALFC, &o0, &o1);
                unsigned long long p = pack_key(o0, j);
                if (p > bp_lo) bp_lo = p;
            }
        }
        int c1 = min(scnt[1], CLS_MAX);
        for (int t = tid; t < c1; t += 256) {
            int j = slist[1][t];
            if (j != i_hi) {
                uint32_t n = nbase + (uint32_t)j, o0, o1;
                threefry2x32(kp0, kp1, n, n + HALFC, &o0, &o1);
                unsigned long long p = pack_key(o1, j);
                if (p > bp_hi) bp_hi = p;
            }
        }
    }

    // ---- warp-level reductions (no barriers) ----
    bp_lo = warp_max_u64(bp_lo);
    bp_hi = warp_max_u64(bp_hi);
    if (lane == 0) { spos[0][wid] = bp_lo; spos[1][wid] = bp_hi; }

    unsigned long long keep_lo = 0ull, keep_hi = 0ull;
    #pragma unroll
    for (int r = 0; r < NNEG; r++) {
        unsigned long long v = warp_max_u64(toplo[0]);
        if (toplo[0] == v && v != 0ull) {            // unique winner pops
            #pragma unroll
            for (int q = 0; q < NNEG - 1; q++) toplo[q] = toplo[q + 1];
            toplo[NNEG - 1] = 0ull;
        }
        if (lane == r) keep_lo = v;
    }
    #pragma unroll
    for (int r = 0; r < NNEG; r++) {
        unsigned long long v = warp_max_u64(tophi[0]);
        if (tophi[0] == v && v != 0ull) {
            #pragma unroll
            for (int q = 0; q < NNEG - 1; q++) tophi[q] = tophi[q + 1];
            tophi[NNEG - 1] = 0ull;
        }
        if (lane == r) keep_hi = v;
    }
    if (lane < NNEG) { swin[0][wid * 8 + lane] = keep_lo; swin[1][wid * 8 + lane] = keep_hi; }
    __syncthreads();

    // ---- final merge: warp 0 -> row lo, warp 1 -> row hi ----
    if (wid < 2) {
        const int row = wid;
        const int i_row = row ? i_hi : i_lo;
        unsigned long long a = swin[row][lane], b = swin[row][lane + 32];
        if (b > a) { unsigned long long t = a; a = b; b = t; }
        #pragma unroll
        for (int r = 0; r < NNEG; r++) {
            unsigned long long v = warp_max_u64(a);
            if (a == v) { a = b; b = 0ull; }         // unique winner pops
            if (lane == 0) g_negidx[i_row * NNEG + r] = NB - 1 - (int)(v & 0x1FFFull);
        }
        unsigned long long bp = (lane < 8) ? spos[row][lane] : 0ull;
        bp = warp_max_u64(bp);
        if (lane == 0)
            g_posj[i_row] = (bp == 0ull) ? 0 : (NB - 1 - (int)(bp & 0x1FFFull));
    }
}

// ---------------- Kernel 3: 9 dots + top-3 + logsumexp + fused mean ----------
__global__ void k_loss(float* __restrict__ out)
{
    int i = blockIdx.x;
    int tid  = threadIdx.x;              // 128 threads
    int lane = tid & 31;
    int w    = tid >> 5;
    __shared__ float sf[ND];
    __shared__ float sdots[12];
    __shared__ int   slast;
    const int n4 = ND >> 2;

    for (int c = tid; c < n4; c += 128)
        ((float4*)sf)[c] = ((const float4*)(g_f + (size_t)i * ND))[c];
    __syncthreads();

    for (int t = w; t < 1 + NNEG; t += 4) {
        int j = (t == 0) ? g_posj[i] : g_negidx[i * NNEG + (t - 1)];
        const float4* fr = (const float4*)(g_f + (size_t)j * ND);
        float acc = 0.0f;
        for (int c = lane; c < n4; c += 32) {
            float4 a = ((float4*)sf)[c];
            float4 b = fr[c];
            acc += a.x * b.x + a.y * b.y + a.z * b.z + a.w * b.w;
        }
        #pragma unroll
        for (int o = 16; o; o >>= 1) acc += __shfl_xor_sync(0xffffffffu, acc, o);
        if (lane == 0) sdots[t] = acc;
    }
    __syncthreads();

    if (tid == 0) {
        float pos = sdots[0] * 2.0f;     // / TEMPERATURE (0.5)
        float s[NNEG];
        #pragma unroll
        for (int q = 0; q < NNEG; q++) s[q] = sdots[1 + q];
        float hard[3];
        #pragma unroll
        for (int r = 0; r < 3; r++) {
            int bi = 0; float bv = s[0];
            #pragma unroll
            for (int q = 1; q < NNEG; q++) if (s[q] > bv) { bv = s[q]; bi = q; }
            hard[r] = bv * 2.0f;
            s[bi] = -3.0e38f;
        }
        float mx = fmaxf(fmaxf(pos, hard[0]), fmaxf(hard[1], hard[2]));
        float sum = expf(pos - mx) + expf(hard[0] - mx) +
                    expf(hard[1] - mx) + expf(hard[2] - mx);
        g_loss[i] = mx + logf(sum) - pos;
    }

    // fused mean: last block to finish reduces g_loss (fixed order -> deterministic)
    if (tid == 0) {
        __threadfence();
        int prev = atomicAdd(&g_done, 1);
        slast = (prev == NB - 1) ? 1 : 0;
    }
    __syncthreads();
    if (slast) {
        float a = 0.0f;
        for (int t = tid; t < NB; t += 128) a += g_loss[t];
        #pragma unroll
        for (int o = 16; o; o >>= 1) a += __shfl_xor_sync(0xffffffffu, a, o);
        __shared__ float sw2[4];
        if ((tid & 31) == 0) sw2[tid >> 5] = a;
        __syncthreads();
        if (tid == 0) {
            out[0] = (sw2[0] + sw2[1] + sw2[2] + sw2[3]) / (float)NB;
            g_done = 0;                  // reset for next graph replay
        }
    }
}

// ---------------- Launch ----------------
extern "C" void kernel_launch(void* const* d_in, const int* in_sizes, int n_in,
                              void* d_out, int out_size)
{
    const float*     feat   = (const float*)d_in[0];
    const long long* labels = (const long long*)d_in[1];

    // seed 42 -> raw key (0, 42); original split: counts iota(4) -> pairs
    // (0,2),(1,3); kp=(a0,a1), kn=(b0,b1)
    uint32_t a0, b0, a1, b1;
    threefry2x32(0u, 42u, 0u, 2u, &a0, &b0);
    threefry2x32(0u, 42u, 1u, 3u, &a1, &b1);
    uint32_t kp0 = a0, kp1 = a1, kn0 = b0, kn1 = b1;

    k_normalize<<<NB, 128>>>(feat, labels);
    k_select  <<<NB / 2, 256>>>(kp0, kp1, kn0, kn1);
    k_loss    <<<NB, 128>>>((float*)d_out);
}

// round 4
// speedup vs baseline: 2.4626x; 2.0541x over previous
#include <cuda_runtime.h>
#include <stdint.h>

// Fixed problem shape: features [8192, 512], labels [8192] in [0,64)
#define NB 8192
#define ND 512
#define NNEG 8
#define HALFC 33554432u        // (8192*8192)/2
#define THRESH_RAW 0xFC000000u // raw-bits threshold == (2^23 * (1-1/64)) << 9
#define NCAP 512               // survivor cap per row (mean 126; P(>512) ~ 0)
#define NSLOT (NCAP / 32)      // 16 u64 slots per lane in extraction
#define CLS 320                // class-list cap (mean 128; P(>320) ~ 0)

// Scratch (no cudaMalloc allowed)
__device__ float         g_f[NB * ND];       // normalized features (16 MB)
__device__ unsigned char g_lab[NB];
__device__ int           g_posj[NB];
__device__ int           g_negidx[NB * NNEG];
__device__ float         g_loss[NB];

// ---------------- Threefry-2x32 (20 rounds), original JAX convention ----------
__host__ __device__ __forceinline__ void threefry2x32(
    uint32_t k0, uint32_t k1, uint32_t x0, uint32_t x1,
    uint32_t* o0, uint32_t* o1)
{
    uint32_t ks2 = k0 ^ k1 ^ 0x1BD11BDAu;
    x0 += k0; x1 += k1;
#define TF_ROTL(v, r) (((v) << (r)) | ((v) >> (32 - (r))))
#define TF_RND(r) { x0 += x1; x1 = TF_ROTL(x1, r); x1 ^= x0; }
    TF_RND(13) TF_RND(15) TF_RND(26) TF_RND(6)  x0 += k1;  x1 += ks2 + 1u;
    TF_RND(17) TF_RND(29) TF_RND(16) TF_RND(24) x0 += ks2; x1 += k0  + 2u;
    TF_RND(13) TF_RND(15) TF_RND(26) TF_RND(6)  x0 += k0;  x1 += k1  + 3u;
    TF_RND(17) TF_RND(29) TF_RND(16) TF_RND(24) x0 += k1;  x1 += ks2 + 4u;
    TF_RND(13) TF_RND(15) TF_RND(26) TF_RND(6)  x0 += ks2; x1 += k0  + 5u;
#undef TF_RND
#undef TF_ROTL
    *o0 = x0; *o1 = x1;
}

// ordering of gumbel == ordering of (bits>>9); tie -> lower j wins.
__device__ __forceinline__ unsigned long long pack_key(uint32_t bits, int j)
{
    return ((unsigned long long)(bits >> 9) << 13) |
           (unsigned long long)(NB - 1 - j);
}

__device__ __forceinline__ unsigned long long warp_max_u64(unsigned long long v)
{
    #pragma unroll
    for (int o = 16; o; o >>= 1) {
        unsigned long long u = __shfl_xor_sync(0xffffffffu, v, o);
        if (u > v) v = u;
    }
    return v;
}

// ---------------- Kernel 1: row L2-normalize + label cast ----------------
__global__ void k_normalize(const float* __restrict__ feat,
                            const long long* __restrict__ labels)
{
    int i = blockIdx.x;
    int tid = threadIdx.x;               // 128 threads
    const float4* src = (const float4*)(feat + (size_t)i * ND);
    float4*       dst = (float4*)(g_f + (size_t)i * ND);
    const int n4 = ND >> 2;

    float ss = 0.0f;
    for (int c = tid; c < n4; c += 128) {
        float4 v = src[c];
        ss += v.x * v.x + v.y * v.y + v.z * v.z + v.w * v.w;
    }
    #pragma unroll
    for (int o = 16; o; o >>= 1) ss += __shfl_xor_sync(0xffffffffu, ss, o);

    __shared__ float sw[4];
    if ((tid & 31) == 0) sw[tid >> 5] = ss;
    __syncthreads();
    float tot = sw[0] + sw[1] + sw[2] + sw[3];
    float inv = 1.0f / fmaxf(sqrtf(tot), 1e-12f);

    for (int c = tid; c < n4; c += 128) {
        float4 v = src[c];
        float4 o4;
        o4.x = v.x * inv; o4.y = v.y * inv; o4.z = v.z * inv; o4.w = v.w * inv;
        dst[c] = o4;
    }
    if (tid == 0) g_lab[i] = (unsigned char)labels[i];
}

// ---------------- Kernel 2: row-PAIR gumbel selection (threshold method) ------
// Block b handles rows i_lo=b, i_hi=b+NB/2 (counter pair shares one threefry:
// o0 -> row lo, o1 -> row hi). Negatives: the row top-8 gumbel keys all lie
// above THRESH (miss prob ~1e-40); survivors (~126/row) go to a shared list;
// exact top-8 by packed u64 key is extracted afterward. Positives handled
// sparsely via per-class lists. Selection semantics identical to R2/R3.
__global__ __launch_bounds__(256) void k_select(
    uint32_t kp0, uint32_t kp1, uint32_t kn0, uint32_t kn1)
{
    const int i_lo = blockIdx.x;           // 0..4095
    const int i_hi = i_lo + (NB >> 1);
    const int tid = threadIdx.x, lane = tid & 31, wid = tid >> 5;

    __shared__ unsigned char slab[NB];                    // 8 KB
    __shared__ unsigned long long nsurv[2][NCAP];         // 8 KB
    __shared__ int ncnt[2];
    __shared__ short clist[2][CLS];                       // 1.25 KB
    __shared__ int ccnt[2];
    __shared__ unsigned long long spos[2][8];

    for (int c = tid; c < NB / 16; c += 256)              // 512 uint4
        ((uint4*)slab)[c] = ((const uint4*)g_lab)[c];
    if (tid < 2) { ncnt[tid] = 0; ccnt[tid] = 0; }
    __syncthreads();

    const unsigned int lab_lo = slab[i_lo];
    const unsigned int lab_hi = slab[i_hi];
    const uint32_t nbase = (uint32_t)i_lo * (uint32_t)NB;

    for (int jb = tid * 4; jb < NB; jb += 1024) {
        uint32_t lw = ((const uint32_t*)slab)[jb >> 2];   // 4 labels
        #pragma unroll
        for (int q = 0; q < 4; q++) {
            int j = jb + q;
            unsigned int lj = (lw >> (8 * q)) & 0xFFu;
            uint32_t n = nbase + (uint32_t)j;
            uint32_t o0, o1;
            threefry2x32(kn0, kn1, n, n + HALFC, &o0, &o1);

            if (lj == lab_lo) {
                int p = atomicAdd(&ccnt[0], 1);
                if (p < CLS) clist[0][p] = (short)j;
            } else if (o0 >= THRESH_RAW) {
                int p = atomicAdd(&ncnt[0], 1);
                if (p < NCAP) nsurv[0][p] = pack_key(o0, j);
            }
            if (lj == lab_hi) {
                int p = atomicAdd(&ccnt[1], 1);
                if (p < CLS) clist[1][p] = (short)j;
            } else if (o1 >= THRESH_RAW) {
                int p = atomicAdd(&ncnt[1], 1);
                if (p < NCAP) nsurv[1][p] = pack_key(o1, j);
            }
        }
    }
    __syncthreads();

    // ---- sparse positive loops (kp key) ----
    unsigned long long bp_lo = 0ull, bp_hi = 0ull;
    {
        int c0 = min(ccnt[0], CLS);
        for (int t = tid; t < c0; t += 256) {
            int j = clist[0][t];
            if (j != i_lo) {
                uint32_t n = nbase + (uint32_t)j, o0, o1;
                threefry2x32(kp0, kp1, n, n + HALFC, &o0, &o1);
                unsigned long long p = pack_key(o0, j);
                if (p > bp_lo) bp_lo = p;
            }
        }
        int c1 = min(ccnt[1], CLS);
        for (int t = tid; t < c1; t += 256) {
            int j = clist[1][t];
            if (j != i_hi) {
                uint32_t n = nbase + (uint32_t)j, o0, o1;
                threefry2x32(kp0, kp1, n, n + HALFC, &o0, &o1);
                unsigned long long p = pack_key(o1, j);
                if (p > bp_hi) bp_hi = p;
            }
        }
    }
    bp_lo = warp_max_u64(bp_lo);
    bp_hi = warp_max_u64(bp_hi);
    if (lane == 0) { spos[0][wid] = bp_lo; spos[1][wid] = bp_hi; }
    __syncthreads();

    // ---- negative top-8 extraction: warp 0 -> row lo, warp 1 -> row hi ----
    if (wid < 2) {
        const int row = wid;
        const int i_row = row ? i_hi : i_lo;
        int cnt = min(ncnt[row], NCAP);

        unsigned long long v[NSLOT];
        #pragma unroll
        for (int s = 0; s < NSLOT; s++) {
            int idx = lane + 32 * s;
            v[s] = (idx < cnt) ? nsurv[row][idx] : 0ull;
        }
        #pragma unroll
        for (int r = 0; r < NNEG; r++) {
            unsigned long long loc = 0ull;
            #pragma unroll
            for (int s = 0; s < NSLOT; s++) if (v[s] > loc) loc = v[s];
            unsigned long long g = warp_max_u64(loc);
            #pragma unroll
            for (int s = 0; s < NSLOT; s++) if (v[s] == g) v[s] = 0ull;  // unique key pops
            if (lane == 0) g_negidx[i_row * NNEG + r] = NB - 1 - (int)(g & 0x1FFFull);
        }

        unsigned long long bp = (lane < 8) ? spos[row][lane] : 0ull;
        bp = warp_max_u64(bp);
        if (lane == 0)
            g_posj[i_row] = (bp == 0ull) ? 0 : (NB - 1 - (int)(bp & 0x1FFFull));
    }
}

// ---------------- Kernel 3: 9 dots + top-3 + logsumexp per row ----------------
__global__ void k_loss()
{
    int i = blockIdx.x;
    int tid  = threadIdx.x;              // 128 threads
    int lane = tid & 31;
    int w    = tid >> 5;
    __shared__ float sf[ND];
    __shared__ float sdots[12];
    const int n4 = ND >> 2;

    for (int c = tid; c < n4; c += 128)
        ((float4*)sf)[c] = ((const float4*)(g_f + (size_t)i * ND))[c];
    __syncthreads();

    for (int t = w; t < 1 + NNEG; t += 4) {
        int j = (t == 0) ? g_posj[i] : g_negidx[i * NNEG + (t - 1)];
        const float4* fr = (const float4*)(g_f + (size_t)j * ND);
        float acc = 0.0f;
        for (int c = lane; c < n4; c += 32) {
            float4 a = ((float4*)sf)[c];
            float4 b = fr[c];
            acc += a.x * b.x + a.y * b.y + a.z * b.z + a.w * b.w;
        }
        #pragma unroll
        for (int o = 16; o; o >>= 1) acc += __shfl_xor_sync(0xffffffffu, acc, o);
        if (lane == 0) sdots[t] = acc;
    }
    __syncthreads();

    if (tid == 0) {
        float pos = sdots[0] * 2.0f;     // / TEMPERATURE (0.5)
        float s[NNEG];
        #pragma unroll
        for (int q = 0; q < NNEG; q++) s[q] = sdots[1 + q];
        float hard[3];
        #pragma unroll
        for (int r = 0; r < 3; r++) {    // stable top-3 (lower index wins ties)
            int bi = 0; float bv = s[0];
            #pragma unroll
            for (int q = 1; q < NNEG; q++) if (s[q] > bv) { bv = s[q]; bi = q; }
            hard[r] = bv * 2.0f;
            s[bi] = -3.0e38f;
        }
        float mx = fmaxf(fmaxf(pos, hard[0]), fmaxf(hard[1], hard[2]));
        float sum = expf(pos - mx) + expf(hard[0] - mx) +
                    expf(hard[1] - mx) + expf(hard[2] - mx);
        g_loss[i] = mx + logf(sum) - pos;
    }
}

// ---------------- Kernel 4: mean reduce (R2 structure, measured 4.94e-4) ------
__global__ void k_reduce(float* __restrict__ out)
{
    __shared__ float s[256];
    int tid = threadIdx.x;
    float a = 0.0f;
    for (int i = tid; i < NB; i += 256) a += g_loss[i];
    s[tid] = a;
    __syncthreads();
    for (int off = 128; off; off >>= 1) {
        if (tid < off) s[tid] += s[tid + off];
        __syncthreads();
    }
    if (tid == 0) out[0] = s[0] / (float)NB;
}

// ---------------- Launch ----------------
extern "C" void kernel_launch(void* const* d_in, const int* in_sizes, int n_in,
                              void* d_out, int out_size)
{
    const float*     feat   = (const float*)d_in[0];
    const long long* labels = (const long long*)d_in[1];

    // seed 42 -> raw key (0, 42); original split: counts iota(4) -> pairs
    // (0,2),(1,3); kp=(a0,a1), kn=(b0,b1)
    uint32_t a0, b0, a1, b1;
    threefry2x32(0u, 42u, 0u, 2u, &a0, &b0);
    threefry2x32(0u, 42u, 1u, 3u, &a1, &b1);
    uint32_t kp0 = a0, kp1 = a1, kn0 = b0, kn1 = b1;

    k_normalize<<<NB, 128>>>(feat, labels);
    k_select  <<<NB / 2, 256>>>(kp0, kp1, kn0, kn1);
    k_loss    <<<NB, 128>>>();
    k_reduce  <<<1, 256>>>((float*)d_out);
}

// round 7
// speedup vs baseline: 2.6420x; 1.0728x over previous
#include <cuda_runtime.h>
#include <stdint.h>

// Fixed problem shape: features [8192, 512], labels [8192] in [0,64)
#define NB 8192
#define ND 512
#define NNEG 8
#define HALFC 33554432u        // (8192*8192)/2
#define THRESH_RAW 0xFC000000u // raw-bits threshold == (2^23 * (1-1/64)) << 9
#define NCAP 512               // survivor cap per row (mean 126; P(>512) ~ 0)
#define NSLOT (NCAP / 32)
#define CLS 320                // class-list cap (mean 128; P(>320) ~ 0)

// Scratch (no cudaMalloc allowed)
__device__ float         g_inv[NB];     // 1/max(||row||,1e-12)
__device__ unsigned char g_lab[NB];
__device__ float         g_loss[NB];

// ---------------- Threefry-2x32 (20 rounds), original JAX convention ----------
__host__ __device__ __forceinline__ void threefry2x32(
    uint32_t k0, uint32_t k1, uint32_t x0, uint32_t x1,
    uint32_t* o0, uint32_t* o1)
{
    uint32_t ks2 = k0 ^ k1 ^ 0x1BD11BDAu;
    x0 += k0; x1 += k1;
#define TF_ROTL(v, r) (((v) << (r)) | ((v) >> (32 - (r))))
#define TF_RND(r) { x0 += x1; x1 = TF_ROTL(x1, r); x1 ^= x0; }
    TF_RND(13) TF_RND(15) TF_RND(26) TF_RND(6)  x0 += k1;  x1 += ks2 + 1u;
    TF_RND(17) TF_RND(29) TF_RND(16) TF_RND(24) x0 += ks2; x1 += k0  + 2u;
    TF_RND(13) TF_RND(15) TF_RND(26) TF_RND(6)  x0 += k0;  x1 += k1  + 3u;
    TF_RND(17) TF_RND(29) TF_RND(16) TF_RND(24) x0 += k1;  x1 += ks2 + 4u;
    TF_RND(13) TF_RND(15) TF_RND(26) TF_RND(6)  x0 += ks2; x1 += k0  + 5u;
#undef TF_RND
#undef TF_ROTL
    *o0 = x0; *o1 = x1;
}

// ordering of gumbel == ordering of (bits>>9); tie -> lower j wins.
__device__ __forceinline__ unsigned long long pack_key(uint32_t bits, int j)
{
    return ((unsigned long long)(bits >> 9) << 13) |
           (unsigned long long)(NB - 1 - j);
}

__device__ __forceinline__ unsigned long long warp_max_u64(unsigned long long v)
{
    #pragma unroll
    for (int o = 16; o; o >>= 1) {
        unsigned long long u = __shfl_xor_sync(0xffffffffu, v, o);
        if (u > v) v = u;
    }
    return v;
}

// ---------------- Kernel 1: inverse norms + label cast ----------------
// One warp per row; 8 rows per 256-thread block.
__global__ __launch_bounds__(256) void k_norms(const float* __restrict__ feat,
                                               const long long* __restrict__ labels)
{
    int row  = blockIdx.x * 8 + (threadIdx.x >> 5);
    int lane = threadIdx.x & 31;
    const float4* src = (const float4*)(feat + (size_t)row * ND);

    float ss = 0.0f;
    #pragma unroll
    for (int k = 0; k < 4; k++) {
        float4 v = src[lane + 32 * k];
        ss += v.x * v.x + v.y * v.y + v.z * v.z + v.w * v.w;
    }
    #pragma unroll
    for (int o = 16; o; o >>= 1) ss += __shfl_xor_sync(0xffffffffu, ss, o);
    if (lane == 0) g_inv[row] = 1.0f / fmaxf(sqrtf(ss), 1e-12f);

    if (threadIdx.x < 8) {
        int r = blockIdx.x * 8 + threadIdx.x;
        g_lab[r] = (unsigned char)labels[r];
    }
}

// ---------------- Kernel 2: row-PAIR selection + fused loss ----------------
// Block b handles rows i_lo=b, i_hi=b+NB/2 (counter pair shares one threefry:
// o0 -> row lo, o1 -> row hi). Selection logic identical to R4 (threshold +
// exact top-8 extraction). Tail: 18 dot products (pos + 8 negs per row) on
// raw features scaled by inv-norms, top-3 negatives, logsumexp -> g_loss.
// NOTE: all vector-accessed shared arrays are declared with their vector type
// (uint4 / float4) so 128-bit LDS/STS alignment holds by construction.
__global__ __launch_bounds__(256) void k_select_loss(
    const float* __restrict__ feat,
    uint32_t kp0, uint32_t kp1, uint32_t kn0, uint32_t kn1)
{
    const int i_lo = blockIdx.x;           // 0..4095
    const int i_hi = i_lo + (NB >> 1);
    const int tid = threadIdx.x, lane = tid & 31, wid = tid >> 5;

    __shared__ uint4 slab4[NB / 16];                      // labels, 8 KB
    __shared__ unsigned long long nsurv[2][NCAP];         // 8 KB
    __shared__ int ncnt[2];
    __shared__ short clist[2][CLS];                       // 1.25 KB
    __shared__ int ccnt[2];
    __shared__ unsigned long long spos[2][8];
    __shared__ int   sidx[2][1 + NNEG];                   // partner indices
    __shared__ float4 srow4[2][ND / 4];                   // anchor rows (4 KB)
    __shared__ float sdots[2][1 + NNEG];

    const unsigned char* slab = (const unsigned char*)slab4;

    for (int c = tid; c < NB / 16; c += 256)
        slab4[c] = ((const uint4*)g_lab)[c];
    if (tid < 2) { ncnt[tid] = 0; ccnt[tid] = 0; }
    __syncthreads();

    const unsigned int lab_lo = slab[i_lo];
    const unsigned int lab_hi = slab[i_hi];
    const uint32_t nbase = (uint32_t)i_lo * (uint32_t)NB;

    // ---- hot loop: 8192 threefry blocks, threshold filter ----
    for (int jb = tid * 4; jb < NB; jb += 1024) {
        uint32_t lw = ((const uint32_t*)slab)[jb >> 2];
        #pragma unroll
        for (int q = 0; q < 4; q++) {
            int j = jb + q;
            unsigned int lj = (lw >> (8 * q)) & 0xFFu;
            uint32_t n = nbase + (uint32_t)j;
            uint32_t o0, o1;
            threefry2x32(kn0, kn1, n, n + HALFC, &o0, &o1);

            if (lj == lab_lo) {
                int p = atomicAdd(&ccnt[0], 1);
                if (p < CLS) clist[0][p] = (short)j;
            } else if (o0 >= THRESH_RAW) {
                int p = atomicAdd(&ncnt[0], 1);
                if (p < NCAP) nsurv[0][p] = pack_key(o0, j);
            }
            if (lj == lab_hi) {
                int p = atomicAdd(&ccnt[1], 1);
                if (p < CLS) clist[1][p] = (short)j;
            } else if (o1 >= THRESH_RAW) {
                int p = atomicAdd(&ncnt[1], 1);
                if (p < NCAP) nsurv[1][p] = pack_key(o1, j);
            }
        }
    }
    __syncthreads();

    // ---- sparse positive loops (kp key) ----
    unsigned long long bp_lo = 0ull, bp_hi = 0ull;
    {
        int c0 = min(ccnt[0], CLS);
        for (int t = tid; t < c0; t += 256) {
            int j = clist[0][t];
            if (j != i_lo) {
                uint32_t n = nbase + (uint32_t)j, o0, o1;
                threefry2x32(kp0, kp1, n, n + HALFC, &o0, &o1);
                unsigned long long p = pack_key(o0, j);
                if (p > bp_lo) bp_lo = p;
            }
        }
        int c1 = min(ccnt[1], CLS);
        for (int t = tid; t < c1; t += 256) {
            int j = clist[1][t];
            if (j != i_hi) {
                uint32_t n = nbase + (uint32_t)j, o0, o1;
                threefry2x32(kp0, kp1, n, n + HALFC, &o0, &o1);
                unsigned long long p = pack_key(o1, j);
                if (p > bp_hi) bp_hi = p;
            }
        }
    }
    bp_lo = warp_max_u64(bp_lo);
    bp_hi = warp_max_u64(bp_hi);
    if (lane == 0) { spos[0][wid] = bp_lo; spos[1][wid] = bp_hi; }
    __syncthreads();

    // ---- parallel tail: warps 0-1 extract top-8 + pos; warps 2-7 preload rows
    if (wid < 2) {
        const int row = wid;
        int cnt = min(ncnt[row], NCAP);
        unsigned long long v[NSLOT];
        #pragma unroll
        for (int s = 0; s < NSLOT; s++) {
            int idx = lane + 32 * s;
            v[s] = (idx < cnt) ? nsurv[row][idx] : 0ull;
        }
        #pragma unroll
        for (int r = 0; r < NNEG; r++) {
            unsigned long long loc = 0ull;
            #pragma unroll
            for (int s = 0; s < NSLOT; s++) if (v[s] > loc) loc = v[s];
            unsigned long long g = warp_max_u64(loc);
            #pragma unroll
            for (int s = 0; s < NSLOT; s++) if (v[s] == g) v[s] = 0ull;  // unique pop
            if (lane == 0) sidx[row][1 + r] = NB - 1 - (int)(g & 0x1FFFull);
        }
        unsigned long long bp = (lane < 8) ? spos[row][lane] : 0ull;
        bp = warp_max_u64(bp);
        if (lane == 0)
            sidx[row][0] = (bp == 0ull) ? 0 : (NB - 1 - (int)(bp & 0x1FFFull));
    } else {
        // load anchor rows i_lo, i_hi (raw) into smem: 256 float4 by 192 threads
        int idx = tid - 64;
        for (int c = idx; c < 2 * (ND / 4); c += 192) {
            int row = c >> 7;                 // 128 float4 per row
            int col = c & 127;
            const int i_row = row ? i_hi : i_lo;
            srow4[row][col] =
                ((const float4*)(feat + (size_t)i_row * ND))[col];
        }
    }
    __syncthreads();

    // ---- 18 dots: warp w handles tasks t = w, w+8, w+16 ----
    const float inv_lo = g_inv[i_lo];
    const float inv_hi = g_inv[i_hi];
    for (int t = wid; t < 2 * (1 + NNEG); t += 8) {
        int row  = t / (1 + NNEG);
        int slot = t % (1 + NNEG);
        int j = sidx[row][slot];
        const float4* fr = (const float4*)(feat + (size_t)j * ND);
        const float4* ar = srow4[row];
        float acc = 0.0f;
        #pragma unroll
        for (int k = 0; k < 4; k++) {
            float4 a = ar[lane + 32 * k];
            float4 b = fr[lane + 32 * k];
            acc += a.x * b.x + a.y * b.y + a.z * b.z + a.w * b.w;
        }
        #pragma unroll
        for (int o = 16; o; o >>= 1) acc += __shfl_xor_sync(0xffffffffu, acc, o);
        if (lane == 0) {
            float inv_i = row ? inv_hi : inv_lo;
            sdots[row][slot] = acc * inv_i * g_inv[j];
        }
    }
    __syncthreads();

    // ---- loss epilogue: thread 0 -> row lo, thread 1 -> row hi ----
    if (tid < 2) {
        const int row = tid;
        const int i_row = row ? i_hi : i_lo;
        float pos = sdots[row][0] * 2.0f;    // / TEMPERATURE (0.5)
        float s[NNEG];
        #pragma unroll
        for (int q = 0; q < NNEG; q++) s[q] = sdots[row][1 + q];
        float hard[3];
        #pragma unroll
        for (int r = 0; r < 3; r++) {        // stable top-3 (lower index wins)
            int bi = 0; float bv = s[0];
            #pragma unroll
            for (int q = 1; q < NNEG; q++) if (s[q] > bv) { bv = s[q]; bi = q; }
            hard[r] = bv * 2.0f;
            s[bi] = -3.0e38f;
        }
        float mx = fmaxf(fmaxf(pos, hard[0]), fmaxf(hard[1], hard[2]));
        float sum = expf(pos - mx) + expf(hard[0] - mx) +
                    expf(hard[1] - mx) + expf(hard[2] - mx);
        g_loss[i_row] = mx + logf(sum) - pos;
    }
}

// ---------------- Kernel 3: mean reduce ----------------
__global__ void k_reduce(float* __restrict__ out)
{
    __shared__ float s[256];
    int tid = threadIdx.x;
    float a = 0.0f;
    for (int i = tid; i < NB; i += 256) a += g_loss[i];
    s[tid] = a;
    __syncthreads();
    for (int off = 128; off; off >>= 1) {
        if (tid < off) s[tid] += s[tid + off];
        __syncthreads();
    }
    if (tid == 0) out[0] = s[0] / (float)NB;
}

// ---------------- Launch ----------------
extern "C" void kernel_launch(void* const* d_in, const int* in_sizes, int n_in,
                              void* d_out, int out_size)
{
    const float*     feat   = (const float*)d_in[0];
    const long long* labels = (const long long*)d_in[1];

    // seed 42 -> raw key (0, 42); original split: counts iota(4) -> pairs
    // (0,2),(1,3); kp=(a0,a1), kn=(b0,b1)
    uint32_t a0, b0, a1, b1;
    threefry2x32(0u, 42u, 0u, 2u, &a0, &b0);
    threefry2x32(0u, 42u, 1u, 3u, &a1, &b1);
    uint32_t kp0 = a0, kp1 = a1, kn0 = b0, kn1 = b1;

    k_norms      <<<NB / 8, 256>>>(feat, labels);
    k_select_loss<<<NB / 2, 256>>>(feat, kp0, kp1, kn0, kn1);
    k_reduce     <<<1, 256>>>((float*)d_out);
}